// round 17
// baseline (speedup 1.0000x reference)
#include <cuda_runtime.h>
#include <math.h>

#define Hn   2048
#define SEQ  2048
#define NBLK 148
#define TPB  544     // 16 worker warps (512) + 1 poller warp
#define WTH  512
#define MAXR 14      // max rows per block: ceil(2048/148)
#define NREP 4       // replicas of the exchange vectors (LTS spread)

// ------------------------------------------------------------------
// Static device scratch (no cudaMalloc allowed)
// ------------------------------------------------------------------
__device__ float d_XF[SEQ * Hn];        // x @ Wfx^T + bfx
__device__ float d_XH[SEQ * Hn];        // x @ Whx^T + bhx
__device__ float d_hbuf[NREP][Hn];      // hidden state, 4 replicas
__device__ float d_gbuf[NREP][Hn];      // f * h, 4 replicas
__device__ unsigned d_count = 0;        // monotonic barrier arrival counter
__device__ unsigned d_base  = 0;        // counter value at start of this run

__device__ __forceinline__ void red_arrive(unsigned* p) {
    asm volatile("red.release.gpu.global.add.u32 [%0], %1;"
                 :: "l"(p), "r"(1u) : "memory");
}
__device__ __forceinline__ unsigned ld_acq(const unsigned* p) {
    unsigned v;
    asm volatile("ld.acquire.gpu.global.u32 %0, [%1];" : "=r"(v) : "l"(p) : "memory");
    return v;
}
// workers-only barrier (16 warps)
__device__ __forceinline__ void bar1() {
    asm volatile("bar.sync 1, %0;" :: "n"(WTH) : "memory");
}
// workers + poller barrier
__device__ __forceinline__ void bar2() {
    asm volatile("bar.sync 2, %0;" :: "n"(TPB) : "memory");
}

// ------------------------------------------------------------------
// Precompute GEMM (R15 quadrant version, frozen).
// ------------------------------------------------------------------
__global__ __launch_bounds__(256, 2) void mgu_gemm(
    const float* __restrict__ x,
    const float* __restrict__ Wfx, const float* __restrict__ bfx,
    const float* __restrict__ Whx, const float* __restrict__ bhx)
{
    const float* __restrict__ W    = (blockIdx.z == 0) ? Wfx : Whx;
    const float* __restrict__ bias = (blockIdx.z == 0) ? bfx : bhx;
    float* __restrict__ C          = (blockIdx.z == 0) ? d_XF : d_XH;

    __shared__ float As[2][16][132];
    __shared__ float Bs[2][16][132];

    const int bm  = blockIdx.y * 128;
    const int bn  = blockIdx.x * 128;
    const int tid = threadIdx.x;
    const int tx  = tid & 15;
    const int ty  = tid >> 4;
    const int ra0 = ty * 4;
    const int ra1 = 64 + ty * 4;
    const int cb0 = tx * 4;
    const int cb1 = 64 + tx * 4;

    int lrow[2], lkq[2];
#pragma unroll
    for (int i = 0; i < 2; i++) {
        int q   = tid + (i << 8);
        lrow[i] = q >> 2;
        lkq[i]  = (q & 3) << 2;
    }

    float4 va[2], vb[2];
#pragma unroll
    for (int i = 0; i < 2; i++) {
        va[i] = *(const float4 *)(x + (size_t)(bm + lrow[i]) * 2048 + lkq[i]);
        vb[i] = *(const float4 *)(W + (size_t)(bn + lrow[i]) * 2048 + lkq[i]);
    }
#pragma unroll
    for (int i = 0; i < 2; i++) {
        As[0][lkq[i] + 0][lrow[i]] = va[i].x; As[0][lkq[i] + 1][lrow[i]] = va[i].y;
        As[0][lkq[i] + 2][lrow[i]] = va[i].z; As[0][lkq[i] + 3][lrow[i]] = va[i].w;
        Bs[0][lkq[i] + 0][lrow[i]] = vb[i].x; Bs[0][lkq[i] + 1][lrow[i]] = vb[i].y;
        Bs[0][lkq[i] + 2][lrow[i]] = vb[i].z; Bs[0][lkq[i] + 3][lrow[i]] = vb[i].w;
    }
    __syncthreads();

    float acc[8][8];
#pragma unroll
    for (int i = 0; i < 8; i++)
#pragma unroll
        for (int j = 0; j < 8; j++) acc[i][j] = 0.f;

    for (int it = 0; it < 128; it++) {
        const int cur = it & 1;
        const int nxt = cur ^ 1;
        const bool more = (it < 127);
        if (more) {
            int k0 = (it + 1) << 4;
#pragma unroll
            for (int i = 0; i < 2; i++) {
                va[i] = *(const float4 *)(x + (size_t)(bm + lrow[i]) * 2048 + k0 + lkq[i]);
                vb[i] = *(const float4 *)(W + (size_t)(bn + lrow[i]) * 2048 + k0 + lkq[i]);
            }
        }
#pragma unroll
        for (int k = 0; k < 16; k++) {
            float a[8], bvv[8];
            *(float4 *)(a)     = *(const float4 *)&As[cur][k][ra0];
            *(float4 *)(a + 4) = *(const float4 *)&As[cur][k][ra1];
            *(float4 *)(bvv)     = *(const float4 *)&Bs[cur][k][cb0];
            *(float4 *)(bvv + 4) = *(const float4 *)&Bs[cur][k][cb1];
#pragma unroll
            for (int i = 0; i < 8; i++)
#pragma unroll
                for (int j = 0; j < 8; j++) acc[i][j] += a[i] * bvv[j];
        }
        if (more) {
#pragma unroll
            for (int i = 0; i < 2; i++) {
                As[nxt][lkq[i] + 0][lrow[i]] = va[i].x; As[nxt][lkq[i] + 1][lrow[i]] = va[i].y;
                As[nxt][lkq[i] + 2][lrow[i]] = va[i].z; As[nxt][lkq[i] + 3][lrow[i]] = va[i].w;
                Bs[nxt][lkq[i] + 0][lrow[i]] = vb[i].x; Bs[nxt][lkq[i] + 1][lrow[i]] = vb[i].y;
                Bs[nxt][lkq[i] + 2][lrow[i]] = vb[i].z; Bs[nxt][lkq[i] + 3][lrow[i]] = vb[i].w;
            }
            __syncthreads();
        }
    }

    float bj[8];
#pragma unroll
    for (int j = 0; j < 4; j++) {
        bj[j]     = __ldg(&bias[bn + cb0 + j]);
        bj[j + 4] = __ldg(&bias[bn + cb1 + j]);
    }
#pragma unroll
    for (int i = 0; i < 8; i++) {
        int row = bm + ((i < 4) ? (ra0 + i) : (ra1 + i - 4));
        float4 v0 = make_float4(acc[i][0] + bj[0], acc[i][1] + bj[1],
                                acc[i][2] + bj[2], acc[i][3] + bj[3]);
        float4 v1 = make_float4(acc[i][4] + bj[4], acc[i][5] + bj[5],
                                acc[i][6] + bj[6], acc[i][7] + bj[7]);
        *(float4 *)(C + (size_t)row * 2048 + bn + cb0) = v0;
        *(float4 *)(C + (size_t)row * 2048 + bn + cb1) = v1;
    }
}

// ------------------------------------------------------------------
// Persistent scan: R6 substrate + 512 workers (one 4-col chunk per
// thread: half the per-thread FMA/load chain, 2x warps for latency
// hiding) + 4x-replicated exchange vectors.
// ------------------------------------------------------------------
__global__ __launch_bounds__(TPB, 1) void mgu_scan(
    const float* __restrict__ h0,
    const float* __restrict__ Wfh, const float* __restrict__ bfh,
    const float* __restrict__ Whf, const float* __restrict__ bhf,
    float* __restrict__ out)
{
    extern __shared__ float sW[];
    __shared__ float sPart[MAXR][16];
    __shared__ float sF[MAXR];
    __shared__ float sHold[MAXR];
    __shared__ float sBfh[MAXR];
    __shared__ float sBhf[MAXR];
    __shared__ unsigned sBase;

    const int b   = blockIdx.x;
    const int tid = threadIdx.x;
    const int r0  = (b * Hn) / NBLK;
    const int r1  = ((b + 1) * Hn) / NBLK;
    const int nr  = r1 - r0;               // 13 or 14

    float* sWf = sW;                        // Wfh rows
    float* sWh = sW + nr * Hn;              // Whf rows

    if (tid == 0) sBase = *(volatile unsigned *)&d_base;

    {   // stage weight rows into SMEM (coalesced float4)
        const float4* gf = (const float4 *)(Wfh + (size_t)r0 * Hn);
        const float4* gh = (const float4 *)(Whf + (size_t)r0 * Hn);
        float4* sf4 = (float4 *)sWf;
        float4* sh4 = (float4 *)sWh;
        const int n4 = nr * (Hn / 4);
        for (int i = tid; i < n4; i += TPB) { sf4[i] = gf[i]; sh4[i] = gh[i]; }
    }
    if (tid < nr) {
        sBfh[tid]  = bfh[r0 + tid];
        sBhf[tid]  = bhf[r0 + tid];
        sHold[tid] = h0[r0 + tid];
    }
    for (int i = b * TPB + tid; i < Hn; i += NBLK * TPB) {
        float v = h0[i];
#pragma unroll
        for (int c = 0; c < NREP; c++) d_hbuf[c][i] = v;
    }

    __syncthreads();
    const unsigned base = sBase;
    if (tid == 0) red_arrive(&d_count);      // gen 1: weights + h0 published

    // ---------------- poller warp (warp 16) ----------------
    if (tid >= WTH) {
        for (unsigned g = 1; g <= 2u * SEQ; g++) {
            if (tid == WTH) {
                unsigned target = base + g * (unsigned)NBLK;
                while ((int)(ld_acq(&d_count) - target) < 0) { }
            }
            bar2();
        }
        if (b == 0 && tid == WTH)
            *(volatile unsigned *)&d_base = base + 2u * SEQ * (unsigned)NBLK;
        return;
    }

    // ---------------- workers (16 warps, 512 threads) ----------------
    const int lane = tid & 31;
    const int wid  = tid >> 5;              // 0..15
    const int c0   = tid * 4;               // this thread's 4-col chunk
    const int rep  = b & (NREP - 1);        // read replica
    const float* hb = d_hbuf[rep];
    const float* gb = d_gbuf[rep];

    float xf_c = 0.f, xh_c = 0.f;
    if (tid < nr) {
        xf_c = __ldg(&d_XF[r0 + tid]);
        xh_c = __ldg(&d_XH[r0 + tid]);
    }

    float4 wr[MAXR];
#pragma unroll
    for (int r = 0; r < MAXR; r++)                   // preload Wfh for t=0
        wr[r] = *(const float4 *)(sWf + r * Hn + c0);
    bar2();                                          // gen 1 synced: h ready

    for (int t = 0; t < SEQ; t++) {
        // ===== phase A : f = sigmoid(xf + Wfh h + bfh);  g = f*h =====
        float4 hv = __ldcg((const float4 *)&hb[c0]);

        float acc[MAXR];
#pragma unroll
        for (int r = 0; r < MAXR; r++)
            acc[r] = wr[r].x * hv.x + wr[r].y * hv.y
                   + wr[r].z * hv.z + wr[r].w * hv.w;

        // paired butterfly reduction: 6 SHFL per 2 rows
#pragma unroll
        for (int p = 0; p < 7; p++) {
            float a = acc[2 * p], c = acc[2 * p + 1];
            a += __shfl_xor_sync(0xffffffffu, a, 16);
            c += __shfl_xor_sync(0xffffffffu, c, 16);
            float m = (lane < 16) ? a : c;
            m += __shfl_xor_sync(0xffffffffu, m, 8);
            m += __shfl_xor_sync(0xffffffffu, m, 4);
            m += __shfl_xor_sync(0xffffffffu, m, 2);
            m += __shfl_xor_sync(0xffffffffu, m, 1);
            if (lane == 0)       sPart[2 * p][wid]     = m;
            else if (lane == 16) sPart[2 * p + 1][wid] = m;
        }
        bar1();
        if (tid < nr) {
            float4 p0 = *(const float4 *)&sPart[tid][0];
            float4 p1 = *(const float4 *)&sPart[tid][4];
            float4 p2 = *(const float4 *)&sPart[tid][8];
            float4 p3 = *(const float4 *)&sPart[tid][12];
            float s = ((p0.x + p0.y) + (p0.z + p0.w))
                    + ((p1.x + p1.y) + (p1.z + p1.w))
                    + ((p2.x + p2.y) + (p2.z + p2.w))
                    + ((p3.x + p3.y) + (p3.z + p3.w));
            float z = s + sBfh[tid] + xf_c;
            float f = 1.f / (1.f + __expf(-z));
            sF[tid] = f;
            float gv = f * sHold[tid];
            int row = r0 + tid;
#pragma unroll
            for (int c = 0; c < NREP; c++) __stcg(&d_gbuf[c][row], gv);
        }
        bar1();
        if (tid == 0) red_arrive(&d_count);          // gen 2t+2
#pragma unroll
        for (int r = 0; r < MAXR; r++)               // preload Whf (hidden under sync)
            wr[r] = *(const float4 *)(sWh + r * Hn + c0);
        bar2();                                      // gen 2t+2 synced: g ready

        // ===== phase B : h_hat = tanh(Whf g + bhf + xh); update =====
        float4 gv4 = __ldcg((const float4 *)&gb[c0]);

        float xf_n = 0.f, xh_n = 0.f;                // prefetch next x-projections
        if (tid < nr && t + 1 < SEQ) {
            xf_n = __ldg(&d_XF[(size_t)(t + 1) * Hn + r0 + tid]);
            xh_n = __ldg(&d_XH[(size_t)(t + 1) * Hn + r0 + tid]);
        }

#pragma unroll
        for (int r = 0; r < MAXR; r++)
            acc[r] = wr[r].x * gv4.x + wr[r].y * gv4.y
                   + wr[r].z * gv4.z + wr[r].w * gv4.w;
#pragma unroll
        for (int p = 0; p < 7; p++) {
            float a = acc[2 * p], c = acc[2 * p + 1];
            a += __shfl_xor_sync(0xffffffffu, a, 16);
            c += __shfl_xor_sync(0xffffffffu, c, 16);
            float m = (lane < 16) ? a : c;
            m += __shfl_xor_sync(0xffffffffu, m, 8);
            m += __shfl_xor_sync(0xffffffffu, m, 4);
            m += __shfl_xor_sync(0xffffffffu, m, 2);
            m += __shfl_xor_sync(0xffffffffu, m, 1);
            if (lane == 0)       sPart[2 * p][wid]     = m;
            else if (lane == 16) sPart[2 * p + 1][wid] = m;
        }
        bar1();
        if (tid < nr) {
            float4 p0 = *(const float4 *)&sPart[tid][0];
            float4 p1 = *(const float4 *)&sPart[tid][4];
            float4 p2 = *(const float4 *)&sPart[tid][8];
            float4 p3 = *(const float4 *)&sPart[tid][12];
            float s = ((p0.x + p0.y) + (p0.z + p0.w))
                    + ((p1.x + p1.y) + (p1.z + p1.w))
                    + ((p2.x + p2.y) + (p2.z + p2.w))
                    + ((p3.x + p3.y) + (p3.z + p3.w));
            float z  = s + sBhf[tid] + xh_c;
            float e2 = __expf(2.f * z);
            float hh = 1.f - 2.f / (e2 + 1.f);      // tanh(z)
            float f  = sF[tid];
            float ho = sHold[tid];
            float hn = ho + f * (hh - ho);          // (1-f)*h + f*h_hat
            sHold[tid] = hn;
            int row = r0 + tid;
            out[(size_t)t * Hn + row] = hn;
#pragma unroll
            for (int c = 0; c < NREP; c++) __stcg(&d_hbuf[c][row], hn);
            if (t == SEQ - 1) out[(size_t)SEQ * Hn + row] = hn;  // h_final
        }
        bar1();
        if (t < SEQ - 1) {
            if (tid == 0) red_arrive(&d_count);      // gen 2t+3
#pragma unroll
            for (int r = 0; r < MAXR; r++)           // preload Wfh for next step
                wr[r] = *(const float4 *)(sWf + r * Hn + c0);
            bar2();                                  // gen 2t+3 synced: h ready
        }
        xf_c = xf_n;
        xh_c = xh_n;
    }
}

// ------------------------------------------------------------------
extern "C" void kernel_launch(void* const* d_in, const int* in_sizes, int n_in,
                              void* d_out, int out_size)
{
    const float* x   = (const float *)d_in[0];
    const float* h0  = (const float *)d_in[1];
    const float* Wfx = (const float *)d_in[2];
    const float* bfx = (const float *)d_in[3];
    const float* Wfh = (const float *)d_in[4];
    const float* bfh = (const float *)d_in[5];
    const float* Whf = (const float *)d_in[6];
    const float* bhf = (const float *)d_in[7];
    const float* Whx = (const float *)d_in[8];
    const float* bhx = (const float *)d_in[9];
    float* out = (float *)d_out;

    (void)in_sizes; (void)n_in; (void)out_size;

    const size_t smem = (size_t)MAXR * Hn * 2 * sizeof(float);  // 229376 B
    cudaFuncSetAttribute(mgu_scan, cudaFuncAttributeMaxDynamicSharedMemorySize,
                         (int)smem);

    mgu_gemm<<<dim3(16, 16, 2), 256>>>(x, Wfx, bfx, Whx, bhx);
    mgu_scan<<<NBLK, TPB, smem>>>(h0, Wfh, bfh, Whf, bhf, out);
}